// round 15
// baseline (speedup 1.0000x reference)
#include <cuda_runtime.h>
#include <cuda_fp16.h>
#include <cstdint>

// ============================================================================
// Problem constants
// ============================================================================
#define M_TOK 32768
#define K_IN  768
#define N_OUT 3072
#define NS    134
#define T_BLOCKS (NS * 144)

// GEMM tiling (single fp16 pass, 2 CTAs/SM, 2-stage pipeline — R13 config)
#define BM 128
#define BN 128
#define BK 64
#define NIT (K_IN / BK)        // 12 iterations
#define M_TILES (M_TOK / BM)   // 256
#define N_TILES (N_OUT / BN)   // 24

#define A_STAGE_BYTES (BM * BK * 2)      // 16384
#define B_STAGE_BYTES (BN * BK * 2)      // 16384
#define STAGE_BYTES (A_STAGE_BYTES + B_STAGE_BYTES)  // 32768
#define NSTAGES 2
#define SMEM_TOTAL (NSTAGES * STAGE_BYTES)           // 65536

// ============================================================================
// Device scratch (allocation-free)
// ============================================================================
__device__ float g_T[(size_t)T_BLOCKS * 128];      // 9.9 MB
__device__ __half g_Ah[(size_t)M_TOK * K_IN];      // 48 MB
__device__ __half g_Bh[(size_t)N_OUT * K_IN];      // 4.5 MB  (W^T as fp16, [n][k])

// ============================================================================
// PTX helpers (plain sm_80+ PTX only)
// ============================================================================
__device__ __forceinline__ uint32_t smem_u32(const void* p) {
    uint32_t a;
    asm("{ .reg .u64 t; cvta.to.shared.u64 t, %1; cvt.u32.u64 %0, t; }" : "=r"(a) : "l"(p));
    return a;
}

__device__ __forceinline__ void cp16(uint32_t dst, const void* src) {
    asm volatile("cp.async.cg.shared.global [%0], [%1], 16;" :: "r"(dst), "l"(src));
}
#define CP_COMMIT() asm volatile("cp.async.commit_group;" ::: "memory")
#define CP_WAIT1()  asm volatile("cp.async.wait_group 1;" ::: "memory")

#define LDMATRIX_X4(r0, r1, r2, r3, addr) \
    asm volatile("ldmatrix.sync.aligned.m8n8.x4.shared.b16 {%0,%1,%2,%3}, [%4];" \
                 : "=r"(r0), "=r"(r1), "=r"(r2), "=r"(r3) : "r"(addr))

#define MMA_F16(d, a0, a1, a2, a3, b0, b1) \
    asm volatile("mma.sync.aligned.m16n8k16.row.col.f32.f16.f16.f32 " \
                 "{%0,%1,%2,%3}, {%4,%5,%6,%7}, {%8,%9}, {%0,%1,%2,%3};" \
                 : "+f"((d)[0]), "+f"((d)[1]), "+f"((d)[2]), "+f"((d)[3]) \
                 : "r"(a0), "r"(a1), "r"(a2), "r"(a3), "r"(b0), "r"(b1))

// 128B-row swizzle: row r, 16B chunk c (0..7) -> c ^ (r & 7).
__device__ __forceinline__ uint32_t swz128(int r, int c) {
    return (uint32_t)(r * 128 + ((c ^ (r & 7)) << 4));
}

// ============================================================================
// Kernel 1: T[s,I,O,a,b] = sum_S W2[s,I,O,S] * W3[S,a,b]
// Block = (s, IO-group of 16). 128 threads (t = ab). Each __ldg of W3 feeds
// 16 FMAs (one per IO in group) -> FMA-issue-bound, minimal crossbar traffic.
// grid = (9, 134).
// ============================================================================
__global__ void compute_T_kernel(const float* __restrict__ W2,
                                 const float* __restrict__ W3) {
    __shared__ float sw2[16 * NS];
    int iog = blockIdx.x;           // 0..8 (16 IO each)
    int s   = blockIdx.y;           // 0..133
    int t   = threadIdx.x;          // 0..127 (ab)

    // Load W2[s, iog*16 .. iog*16+15, :] into smem (2144 floats)
    const float* w2p = W2 + ((size_t)s * 144 + iog * 16) * NS;
    for (int j = t; j < 16 * NS; j += 128) sw2[j] = w2p[j];
    __syncthreads();

    float acc[16];
#pragma unroll
    for (int io = 0; io < 16; io++) acc[io] = 0.f;

#pragma unroll 2
    for (int S = 0; S < NS; S++) {
        float w3 = __ldg(&W3[S * 128 + t]);
#pragma unroll
        for (int io = 0; io < 16; io++)
            acc[io] += sw2[io * NS + S] * w3;
    }

#pragma unroll
    for (int io = 0; io < 16; io++)
        g_T[((size_t)s * 144 + iog * 16 + io) * 128 + t] = acc[io];
}

// ============================================================================
// Kernel 2 (fused): W^T directly to fp16 — g_Bh[c*768 + r] = fp16(sum_s ...)
//           r=(i*12+I)*8+a, c=(o*12+O)*16+b
// ============================================================================
__global__ void compute_Wt_kernel(const float* __restrict__ W1) {
    int IO = blockIdx.x;
    int I = IO / 12, O = IO % 12;
    int t = threadIdx.x;
    int o = t >> 4, b = t & 15;

    __shared__ float sW1[32][128];
    __shared__ float sT[32][128];

    float acc[64];
#pragma unroll
    for (int i = 0; i < 64; i++) acc[i] = 0.f;

    for (int s0 = 0; s0 < NS; s0 += 32) {
        int ns = min(32, NS - s0);
        for (int j = t; j < ns * 128; j += 256) {
            int ss = j >> 7, io = j & 127;
            sW1[ss][io] = W1[io * NS + s0 + ss];
        }
        for (int j = t; j < ns * 128; j += 256) {
            int ss = j >> 7, ab = j & 127;
            sT[ss][ab] = g_T[((size_t)(s0 + ss) * 144 + IO) * 128 + ab];
        }
        __syncthreads();
        for (int ss = 0; ss < ns; ss++) {
            float w1v[8], tv[8];
#pragma unroll
            for (int i = 0; i < 8; i++) w1v[i] = sW1[ss][i * 16 + o];
#pragma unroll
            for (int a = 0; a < 8; a++) tv[a] = sT[ss][a * 16 + b];
#pragma unroll
            for (int i = 0; i < 8; i++)
#pragma unroll
                for (int a = 0; a < 8; a++)
                    acc[i * 8 + a] += w1v[i] * tv[a];
        }
        __syncthreads();
    }

    int c = (o * 12 + O) * 16 + b;
#pragma unroll
    for (int i = 0; i < 8; i++)
#pragma unroll
        for (int a = 0; a < 8; a++) {
            int r = (i * 12 + I) * 8 + a;
            g_Bh[(size_t)c * K_IN + r] = __float2half_rn(acc[i * 8 + a]);
        }
}

// ============================================================================
// Kernel 3: x (fp32) -> fp16, 16 elements per thread, 512-thread blocks.
// ============================================================================
__global__ void convert_x_kernel(const float* __restrict__ x) {
    size_t gt = (size_t)blockIdx.x * blockDim.x + threadIdx.x;  // 0 .. M*K/16-1
    const float* xp = x + gt * 16;
    uint32_t hw[8];
#pragma unroll
    for (int h = 0; h < 2; h++) {
        float4 v0 = *reinterpret_cast<const float4*>(xp + h * 8);
        float4 v1 = *reinterpret_cast<const float4*>(xp + h * 8 + 4);
        float f[8] = {v0.x, v0.y, v0.z, v0.w, v1.x, v1.y, v1.z, v1.w};
#pragma unroll
        for (int j = 0; j < 4; j++) {
            __half2 hh = __floats2half2_rn(f[2*j], f[2*j+1]);
            hw[h * 4 + j] = *reinterpret_cast<uint32_t*>(&hh);
        }
    }
    *reinterpret_cast<uint4*>(&g_Ah[gt * 16])     = make_uint4(hw[0], hw[1], hw[2], hw[3]);
    *reinterpret_cast<uint4*>(&g_Ah[gt * 16 + 8]) = make_uint4(hw[4], hw[5], hw[6], hw[7]);
}

// ============================================================================
// Kernel 4: GEMM via mma.sync fp16 (fp32 accum). 256 threads = 8 warps
// (2m x 4n), warp tile 64x32, BK=64, 2-stage cp.async, 2 CTAs/SM.  (R13)
// ============================================================================
__global__ __launch_bounds__(256, 2)
void gemm_mma_kernel(const float* __restrict__ bias, float* __restrict__ C) {
    extern __shared__ unsigned char smem[];
    const uint32_t sbase = smem_u32(smem);

    const int tid  = threadIdx.x;
    const int wid  = tid >> 5;
    const int lane = tid & 31;
    const int m0 = blockIdx.y * BM;
    const int n0 = blockIdx.x * BN;
    const int warp_m = (wid & 1) * 64;   // 0,64
    const int warp_n = (wid >> 1) * 32;  // 0,32,64,96

    float acc[4][4][4];
#pragma unroll
    for (int i = 0; i < 4; i++)
#pragma unroll
        for (int j = 0; j < 4; j++)
#pragma unroll
            for (int q = 0; q < 4; q++) acc[i][j][q] = 0.f;

    // ---- stage loader: A 1024 chunks (4/thread), B 1024 chunks (4/thread) ----
    auto load_stage = [&](int stage, int it) {
        int k0 = it * BK;
        uint32_t sA = sbase + stage * STAGE_BYTES;
        uint32_t sB = sA + A_STAGE_BYTES;
#pragma unroll
        for (int j = 0; j < 4; j++) {
            int id  = tid + j * 256;
            int row = id >> 3;
            int c   = id & 7;
            cp16(sA + swz128(row, c), g_Ah + (size_t)(m0 + row) * K_IN + k0 + c * 8);
        }
#pragma unroll
        for (int j = 0; j < 4; j++) {
            int id  = tid + j * 256;
            int row = id >> 3;
            int c   = id & 7;
            cp16(sB + swz128(row, c), g_Bh + (size_t)(n0 + row) * K_IN + k0 + c * 8);
        }
    };

    const int fr = lane & 15;
    const int fc = lane >> 4;

    // Prologue: stage 0
    load_stage(0, 0); CP_COMMIT();

    for (int it = 0; it < NIT; it++) {
        __syncthreads();           // all warps done computing iter it-1 (buffer (it+1)&1)
        if (it + 1 < NIT) load_stage((it + 1) & 1, it + 1);
        CP_COMMIT();
        CP_WAIT1();                // stage it&1 landed (lookahead group may fly)
        __syncthreads();           // cross-thread visibility of stage it&1

        uint32_t sA = sbase + (it & 1) * STAGE_BYTES;
        uint32_t sB = sA + A_STAGE_BYTES;

#pragma unroll
        for (int ks = 0; ks < 4; ks++) {
            uint32_t aF[4][4];
#pragma unroll
            for (int mt = 0; mt < 4; mt++) {
                int r = warp_m + mt * 16 + fr;
                LDMATRIX_X4(aF[mt][0], aF[mt][1], aF[mt][2], aF[mt][3],
                            sA + swz128(r, ks * 2 + fc));
            }
            uint32_t bF[2][4];
#pragma unroll
            for (int nt = 0; nt < 2; nt++) {
                int r = warp_n + nt * 16 + fr;
                LDMATRIX_X4(bF[nt][0], bF[nt][1], bF[nt][2], bF[nt][3],
                            sB + swz128(r, ks * 2 + fc));
            }
#pragma unroll
            for (int mt = 0; mt < 4; mt++)
#pragma unroll
                for (int nt = 0; nt < 2; nt++)
#pragma unroll
                    for (int p = 0; p < 2; p++) {
                        MMA_F16(acc[mt][nt * 2 + p],
                                aF[mt][0], aF[mt][1], aF[mt][2], aF[mt][3],
                                bF[nt][p], bF[nt][2 + p]);
                    }
        }
    }

    // ---- Epilogue: bias + store ----
    const int g = lane >> 2, tig = lane & 3;
    float bv[4][2];
#pragma unroll
    for (int nn = 0; nn < 4; nn++) {
        int col = n0 + warp_n + nn * 8 + tig * 2;
        bv[nn][0] = __ldg(&bias[col]);
        bv[nn][1] = __ldg(&bias[col + 1]);
    }
#pragma unroll
    for (int mt = 0; mt < 4; mt++) {
        int r0 = m0 + warp_m + mt * 16 + g;
        int r1 = r0 + 8;
#pragma unroll
        for (int nn = 0; nn < 4; nn++) {
            int col = n0 + warp_n + nn * 8 + tig * 2;
            float2 v0 = make_float2(acc[mt][nn][0] + bv[nn][0], acc[mt][nn][1] + bv[nn][1]);
            float2 v1 = make_float2(acc[mt][nn][2] + bv[nn][0], acc[mt][nn][3] + bv[nn][1]);
            *reinterpret_cast<float2*>(&C[(size_t)r0 * N_OUT + col]) = v0;
            *reinterpret_cast<float2*>(&C[(size_t)r1 * N_OUT + col]) = v1;
        }
    }
}

// ============================================================================
// Launch. Inputs: x, W_1, W_2, W_3, b. Output fp32 (32768, 3072).
// ============================================================================
extern "C" void kernel_launch(void* const* d_in, const int* in_sizes, int n_in,
                              void* d_out, int out_size) {
    const float* x  = (const float*)d_in[0];
    const float* W1 = (const float*)d_in[1];
    const float* W2 = (const float*)d_in[2];
    const float* W3 = (const float*)d_in[3];
    const float* b  = (const float*)d_in[4];
    float* out = (float*)d_out;

    cudaFuncSetAttribute(gemm_mma_kernel,
                         cudaFuncAttributeMaxDynamicSharedMemorySize, SMEM_TOTAL);

    compute_T_kernel<<<dim3(9, NS), 128>>>(W2, W3);
    compute_Wt_kernel<<<144, 256>>>(W1);
    convert_x_kernel<<<(M_TOK * 48) / 512, 512>>>(x);
    gemm_mma_kernel<<<dim3(N_TILES, M_TILES), 256, SMEM_TOTAL>>>(b, out);
}

// round 16
// speedup vs baseline: 1.5220x; 1.5220x over previous
#include <cuda_runtime.h>
#include <cuda_fp16.h>
#include <cstdint>

// ============================================================================
// Problem constants
// ============================================================================
#define M_TOK 32768
#define K_IN  768
#define N_OUT 3072
#define NS    134
#define T_BLOCKS (NS * 144)

// GEMM tiling (single fp16 pass, 2 CTAs/SM, 2-stage pipeline — R13 config)
#define BM 128
#define BN 128
#define BK 64
#define NIT (K_IN / BK)        // 12 iterations
#define M_TILES (M_TOK / BM)   // 256
#define N_TILES (N_OUT / BN)   // 24

#define A_STAGE_BYTES (BM * BK * 2)      // 16384
#define B_STAGE_BYTES (BN * BK * 2)      // 16384
#define STAGE_BYTES (A_STAGE_BYTES + B_STAGE_BYTES)  // 32768
#define NSTAGES 2
#define SMEM_TOTAL (NSTAGES * STAGE_BYTES)           // 65536

// ============================================================================
// Device scratch (allocation-free)
// ============================================================================
__device__ float g_T[(size_t)T_BLOCKS * 128];      // 9.9 MB
__device__ __half g_Ah[(size_t)M_TOK * K_IN];      // 48 MB
__device__ __half g_Bh[(size_t)N_OUT * K_IN];      // 4.5 MB  (W^T as fp16, [n][k])

// ============================================================================
// PTX helpers (plain sm_80+ PTX only)
// ============================================================================
__device__ __forceinline__ uint32_t smem_u32(const void* p) {
    uint32_t a;
    asm("{ .reg .u64 t; cvta.to.shared.u64 t, %1; cvt.u32.u64 %0, t; }" : "=r"(a) : "l"(p));
    return a;
}

__device__ __forceinline__ void cp16(uint32_t dst, const void* src) {
    asm volatile("cp.async.cg.shared.global [%0], [%1], 16;" :: "r"(dst), "l"(src));
}
#define CP_COMMIT() asm volatile("cp.async.commit_group;" ::: "memory")
#define CP_WAIT1()  asm volatile("cp.async.wait_group 1;" ::: "memory")

#define LDMATRIX_X4(r0, r1, r2, r3, addr) \
    asm volatile("ldmatrix.sync.aligned.m8n8.x4.shared.b16 {%0,%1,%2,%3}, [%4];" \
                 : "=r"(r0), "=r"(r1), "=r"(r2), "=r"(r3) : "r"(addr))

#define MMA_F16(d, a0, a1, a2, a3, b0, b1) \
    asm volatile("mma.sync.aligned.m16n8k16.row.col.f32.f16.f16.f32 " \
                 "{%0,%1,%2,%3}, {%4,%5,%6,%7}, {%8,%9}, {%0,%1,%2,%3};" \
                 : "+f"((d)[0]), "+f"((d)[1]), "+f"((d)[2]), "+f"((d)[3]) \
                 : "r"(a0), "r"(a1), "r"(a2), "r"(a3), "r"(b0), "r"(b1))

// 128B-row swizzle: row r, 16B chunk c (0..7) -> c ^ (r & 7).
__device__ __forceinline__ uint32_t swz128(int r, int c) {
    return (uint32_t)(r * 128 + ((c ^ (r & 7)) << 4));
}

// ============================================================================
// Kernel 1: T[s,I,O,a,b] = sum_S W2[s,I,O,S] * W3[S,a,b]
// Block = (s, IO-group of 16). 128 threads (t = ab). Each __ldg of W3 feeds
// 16 FMAs -> FMA-issue-bound, minimal crossbar traffic. grid = (9, 134).
// ============================================================================
__global__ void compute_T_kernel(const float* __restrict__ W2,
                                 const float* __restrict__ W3) {
    __shared__ float sw2[16 * NS];
    int iog = blockIdx.x;           // 0..8 (16 IO each)
    int s   = blockIdx.y;           // 0..133
    int t   = threadIdx.x;          // 0..127 (ab)

    const float* w2p = W2 + ((size_t)s * 144 + iog * 16) * NS;
    for (int j = t; j < 16 * NS; j += 128) sw2[j] = w2p[j];
    __syncthreads();

    float acc[16];
#pragma unroll
    for (int io = 0; io < 16; io++) acc[io] = 0.f;

#pragma unroll 2
    for (int S = 0; S < NS; S++) {
        float w3 = __ldg(&W3[S * 128 + t]);
#pragma unroll
        for (int io = 0; io < 16; io++)
            acc[io] += sw2[io * NS + S] * w3;
    }

#pragma unroll
    for (int io = 0; io < 16; io++)
        g_T[((size_t)s * 144 + iog * 16 + io) * 128 + t] = acc[io];
}

// ============================================================================
// Kernel 2 (fused): W^T directly to fp16 — g_Bh[c*768 + r] = fp16(sum_s ...)
//           r=(i*12+I)*8+a, c=(o*12+O)*16+b
// ============================================================================
__global__ void compute_Wt_kernel(const float* __restrict__ W1) {
    int IO = blockIdx.x;
    int I = IO / 12, O = IO % 12;
    int t = threadIdx.x;
    int o = t >> 4, b = t & 15;

    __shared__ float sW1[32][128];
    __shared__ float sT[32][128];

    float acc[64];
#pragma unroll
    for (int i = 0; i < 64; i++) acc[i] = 0.f;

    for (int s0 = 0; s0 < NS; s0 += 32) {
        int ns = min(32, NS - s0);
        for (int j = t; j < ns * 128; j += 256) {
            int ss = j >> 7, io = j & 127;
            sW1[ss][io] = W1[io * NS + s0 + ss];
        }
        for (int j = t; j < ns * 128; j += 256) {
            int ss = j >> 7, ab = j & 127;
            sT[ss][ab] = g_T[((size_t)(s0 + ss) * 144 + IO) * 128 + ab];
        }
        __syncthreads();
        for (int ss = 0; ss < ns; ss++) {
            float w1v[8], tv[8];
#pragma unroll
            for (int i = 0; i < 8; i++) w1v[i] = sW1[ss][i * 16 + o];
#pragma unroll
            for (int a = 0; a < 8; a++) tv[a] = sT[ss][a * 16 + b];
#pragma unroll
            for (int i = 0; i < 8; i++)
#pragma unroll
                for (int a = 0; a < 8; a++)
                    acc[i * 8 + a] += w1v[i] * tv[a];
        }
        __syncthreads();
    }

    int c = (o * 12 + O) * 16 + b;
#pragma unroll
    for (int i = 0; i < 8; i++)
#pragma unroll
        for (int a = 0; a < 8; a++) {
            int r = (i * 12 + I) * 8 + a;
            g_Bh[(size_t)c * K_IN + r] = __float2half_rn(acc[i * 8 + a]);
        }
}

// ============================================================================
// Kernel 3: x (fp32) -> fp16, 16 elements per thread, 512-thread blocks.
// ============================================================================
__global__ void convert_x_kernel(const float* __restrict__ x) {
    size_t gt = (size_t)blockIdx.x * blockDim.x + threadIdx.x;  // 0 .. M*K/16-1
    const float* xp = x + gt * 16;
    uint32_t hw[8];
#pragma unroll
    for (int h = 0; h < 2; h++) {
        float4 v0 = *reinterpret_cast<const float4*>(xp + h * 8);
        float4 v1 = *reinterpret_cast<const float4*>(xp + h * 8 + 4);
        float f[8] = {v0.x, v0.y, v0.z, v0.w, v1.x, v1.y, v1.z, v1.w};
#pragma unroll
        for (int j = 0; j < 4; j++) {
            __half2 hh = __floats2half2_rn(f[2*j], f[2*j+1]);
            hw[h * 4 + j] = *reinterpret_cast<uint32_t*>(&hh);
        }
    }
    *reinterpret_cast<uint4*>(&g_Ah[gt * 16])     = make_uint4(hw[0], hw[1], hw[2], hw[3]);
    *reinterpret_cast<uint4*>(&g_Ah[gt * 16 + 8]) = make_uint4(hw[4], hw[5], hw[6], hw[7]);
}

// ============================================================================
// Kernel 4: GEMM via mma.sync fp16 (fp32 accum). 256 threads = 8 warps
// (2m x 4n), warp tile 64x32, BK=64, 2-stage cp.async, 2 CTAs/SM. (R13)
// C stores use __stcs (evict-first) — C is write-once, keep it out of L2.
// ============================================================================
__global__ __launch_bounds__(256, 2)
void gemm_mma_kernel(const float* __restrict__ bias, float* __restrict__ C) {
    extern __shared__ unsigned char smem[];
    const uint32_t sbase = smem_u32(smem);

    const int tid  = threadIdx.x;
    const int wid  = tid >> 5;
    const int lane = tid & 31;
    const int m0 = blockIdx.y * BM;
    const int n0 = blockIdx.x * BN;
    const int warp_m = (wid & 1) * 64;   // 0,64
    const int warp_n = (wid >> 1) * 32;  // 0,32,64,96

    float acc[4][4][4];
#pragma unroll
    for (int i = 0; i < 4; i++)
#pragma unroll
        for (int j = 0; j < 4; j++)
#pragma unroll
            for (int q = 0; q < 4; q++) acc[i][j][q] = 0.f;

    // ---- stage loader: A 1024 chunks (4/thread), B 1024 chunks (4/thread) ----
    auto load_stage = [&](int stage, int it) {
        int k0 = it * BK;
        uint32_t sA = sbase + stage * STAGE_BYTES;
        uint32_t sB = sA + A_STAGE_BYTES;
#pragma unroll
        for (int j = 0; j < 4; j++) {
            int id  = tid + j * 256;
            int row = id >> 3;
            int c   = id & 7;
            cp16(sA + swz128(row, c), g_Ah + (size_t)(m0 + row) * K_IN + k0 + c * 8);
        }
#pragma unroll
        for (int j = 0; j < 4; j++) {
            int id  = tid + j * 256;
            int row = id >> 3;
            int c   = id & 7;
            cp16(sB + swz128(row, c), g_Bh + (size_t)(n0 + row) * K_IN + k0 + c * 8);
        }
    };

    const int fr = lane & 15;
    const int fc = lane >> 4;

    // Prologue: stage 0
    load_stage(0, 0); CP_COMMIT();

    for (int it = 0; it < NIT; it++) {
        __syncthreads();           // all warps done computing iter it-1 (buffer (it+1)&1)
        if (it + 1 < NIT) load_stage((it + 1) & 1, it + 1);
        CP_COMMIT();
        CP_WAIT1();                // stage it&1 landed (lookahead group may fly)
        __syncthreads();           // cross-thread visibility of stage it&1

        uint32_t sA = sbase + (it & 1) * STAGE_BYTES;
        uint32_t sB = sA + A_STAGE_BYTES;

#pragma unroll
        for (int ks = 0; ks < 4; ks++) {
            uint32_t aF[4][4];
#pragma unroll
            for (int mt = 0; mt < 4; mt++) {
                int r = warp_m + mt * 16 + fr;
                LDMATRIX_X4(aF[mt][0], aF[mt][1], aF[mt][2], aF[mt][3],
                            sA + swz128(r, ks * 2 + fc));
            }
            uint32_t bF[2][4];
#pragma unroll
            for (int nt = 0; nt < 2; nt++) {
                int r = warp_n + nt * 16 + fr;
                LDMATRIX_X4(bF[nt][0], bF[nt][1], bF[nt][2], bF[nt][3],
                            sB + swz128(r, ks * 2 + fc));
            }
#pragma unroll
            for (int mt = 0; mt < 4; mt++)
#pragma unroll
                for (int nt = 0; nt < 2; nt++)
#pragma unroll
                    for (int p = 0; p < 2; p++) {
                        MMA_F16(acc[mt][nt * 2 + p],
                                aF[mt][0], aF[mt][1], aF[mt][2], aF[mt][3],
                                bF[nt][p], bF[nt][2 + p]);
                    }
        }
    }

    // ---- Epilogue: bias + streaming store (evict-first, C never re-read) ----
    const int g = lane >> 2, tig = lane & 3;
    float bv[4][2];
#pragma unroll
    for (int nn = 0; nn < 4; nn++) {
        int col = n0 + warp_n + nn * 8 + tig * 2;
        bv[nn][0] = __ldg(&bias[col]);
        bv[nn][1] = __ldg(&bias[col + 1]);
    }
#pragma unroll
    for (int mt = 0; mt < 4; mt++) {
        int r0 = m0 + warp_m + mt * 16 + g;
        int r1 = r0 + 8;
#pragma unroll
        for (int nn = 0; nn < 4; nn++) {
            int col = n0 + warp_n + nn * 8 + tig * 2;
            float2 v0 = make_float2(acc[mt][nn][0] + bv[nn][0], acc[mt][nn][1] + bv[nn][1]);
            float2 v1 = make_float2(acc[mt][nn][2] + bv[nn][0], acc[mt][nn][3] + bv[nn][1]);
            __stcs(reinterpret_cast<float2*>(&C[(size_t)r0 * N_OUT + col]), v0);
            __stcs(reinterpret_cast<float2*>(&C[(size_t)r1 * N_OUT + col]), v1);
        }
    }
}

// ============================================================================
// Launch. Inputs: x, W_1, W_2, W_3, b. Output fp32 (32768, 3072).
// ============================================================================
extern "C" void kernel_launch(void* const* d_in, const int* in_sizes, int n_in,
                              void* d_out, int out_size) {
    const float* x  = (const float*)d_in[0];
    const float* W1 = (const float*)d_in[1];
    const float* W2 = (const float*)d_in[2];
    const float* W3 = (const float*)d_in[3];
    const float* b  = (const float*)d_in[4];
    float* out = (float*)d_out;

    cudaFuncSetAttribute(gemm_mma_kernel,
                         cudaFuncAttributeMaxDynamicSharedMemorySize, SMEM_TOTAL);

    compute_T_kernel<<<dim3(9, NS), 128>>>(W2, W3);
    compute_Wt_kernel<<<144, 256>>>(W1);
    convert_x_kernel<<<(M_TOK * 48) / 512, 512>>>(x);
    gemm_mma_kernel<<<dim3(N_TILES, M_TILES), 256, SMEM_TOTAL>>>(b, out);
}

// round 17
// speedup vs baseline: 1.5536x; 1.0207x over previous
#include <cuda_runtime.h>
#include <cuda_fp16.h>
#include <cstdint>

// ============================================================================
// Problem constants
// ============================================================================
#define M_TOK 32768
#define K_IN  768
#define N_OUT 3072
#define NS    134
#define T_BLOCKS (NS * 144)

// GEMM tiling (single fp16 pass, 2 CTAs/SM, 2-stage pipeline)
#define BM 128
#define BN 128
#define BK 64
#define NIT (K_IN / BK)        // 12 iterations
#define M_TILES (M_TOK / BM)   // 256
#define N_TILES (N_OUT / BN)   // 24

#define A_STAGE_BYTES (BM * BK * 2)      // 16384
#define B_STAGE_BYTES (BN * BK * 2)      // 16384
#define STAGE_BYTES (A_STAGE_BYTES + B_STAGE_BYTES)  // 32768
#define NSTAGES 2
#define SMEM_TOTAL (NSTAGES * STAGE_BYTES)           // 65536

// Fat kernel 1 split: convert_x blocks then compute_T blocks
#define CVT_BLOCKS (M_TOK * K_IN / 16 / 128)   // 12288 (128 thr x 16 elem)
#define T_GRID_BLOCKS (9 * NS)                 // 1206  (16 IO per block)

// ============================================================================
// Device scratch (allocation-free)
// ============================================================================
__device__ float g_T[(size_t)T_BLOCKS * 128];      // 9.9 MB
__device__ __half g_Ah[(size_t)M_TOK * K_IN];      // 48 MB
__device__ __half g_Bh[(size_t)N_OUT * K_IN];      // 4.5 MB  (W^T as fp16, [n][k])

// ============================================================================
// PTX helpers (plain sm_80+ PTX only)
// ============================================================================
__device__ __forceinline__ uint32_t smem_u32(const void* p) {
    uint32_t a;
    asm("{ .reg .u64 t; cvta.to.shared.u64 t, %1; cvt.u32.u64 %0, t; }" : "=r"(a) : "l"(p));
    return a;
}

__device__ __forceinline__ void cp16(uint32_t dst, const void* src) {
    asm volatile("cp.async.cg.shared.global [%0], [%1], 16;" :: "r"(dst), "l"(src));
}
#define CP_COMMIT() asm volatile("cp.async.commit_group;" ::: "memory")
#define CP_WAIT1()  asm volatile("cp.async.wait_group 1;" ::: "memory")

#define LDMATRIX_X4(r0, r1, r2, r3, addr) \
    asm volatile("ldmatrix.sync.aligned.m8n8.x4.shared.b16 {%0,%1,%2,%3}, [%4];" \
                 : "=r"(r0), "=r"(r1), "=r"(r2), "=r"(r3) : "r"(addr))

#define MMA_F16(d, a0, a1, a2, a3, b0, b1) \
    asm volatile("mma.sync.aligned.m16n8k16.row.col.f32.f16.f16.f32 " \
                 "{%0,%1,%2,%3}, {%4,%5,%6,%7}, {%8,%9}, {%0,%1,%2,%3};" \
                 : "+f"((d)[0]), "+f"((d)[1]), "+f"((d)[2]), "+f"((d)[3]) \
                 : "r"(a0), "r"(a1), "r"(a2), "r"(a3), "r"(b0), "r"(b1))

// 128B-row swizzle: row r, 16B chunk c (0..7) -> c ^ (r & 7).
__device__ __forceinline__ uint32_t swz128(int r, int c) {
    return (uint32_t)(r * 128 + ((c ^ (r & 7)) << 4));
}

// ============================================================================
// Kernel 1 (fat): blocks [0, CVT_BLOCKS) convert x->fp16;
//                 blocks [CVT_BLOCKS, +T_GRID_BLOCKS) compute T.
// Overlaps DRAM-bound convert with FMA-bound T contraction.
// ============================================================================
__global__ void prep_kernel(const float* __restrict__ x,
                            const float* __restrict__ W2,
                            const float* __restrict__ W3) {
    __shared__ float sw2[16 * NS];
    int blk = blockIdx.x;
    int t   = threadIdx.x;          // 0..127

    if (blk < CVT_BLOCKS) {
        // ---- convert_x: 16 elements per thread ----
        size_t gt = (size_t)blk * 128 + t;
        const float* xp = x + gt * 16;
        uint32_t hw[8];
#pragma unroll
        for (int h = 0; h < 2; h++) {
            float4 v0 = *reinterpret_cast<const float4*>(xp + h * 8);
            float4 v1 = *reinterpret_cast<const float4*>(xp + h * 8 + 4);
            float f[8] = {v0.x, v0.y, v0.z, v0.w, v1.x, v1.y, v1.z, v1.w};
#pragma unroll
            for (int j = 0; j < 4; j++) {
                __half2 hh = __floats2half2_rn(f[2*j], f[2*j+1]);
                hw[h * 4 + j] = *reinterpret_cast<uint32_t*>(&hh);
            }
        }
        *reinterpret_cast<uint4*>(&g_Ah[gt * 16])     = make_uint4(hw[0], hw[1], hw[2], hw[3]);
        *reinterpret_cast<uint4*>(&g_Ah[gt * 16 + 8]) = make_uint4(hw[4], hw[5], hw[6], hw[7]);
        return;
    }

    // ---- compute_T: T[s,IO,ab] = sum_S W2[s,IO,S]*W3[S,ab], 16 IO/block ----
    int tb  = blk - CVT_BLOCKS;
    int iog = tb % 9;               // 0..8
    int s   = tb / 9;               // 0..133

    const float* w2p = W2 + ((size_t)s * 144 + iog * 16) * NS;
    for (int j = t; j < 16 * NS; j += 128) sw2[j] = w2p[j];
    __syncthreads();

    float acc[16];
#pragma unroll
    for (int io = 0; io < 16; io++) acc[io] = 0.f;

#pragma unroll 2
    for (int S = 0; S < NS; S++) {
        float w3 = __ldg(&W3[S * 128 + t]);
#pragma unroll
        for (int io = 0; io < 16; io++)
            acc[io] += sw2[io * NS + S] * w3;
    }

#pragma unroll
    for (int io = 0; io < 16; io++)
        g_T[((size_t)s * 144 + iog * 16 + io) * 128 + t] = acc[io];
}

// ============================================================================
// Kernel 2 (fused): W^T directly to fp16 — g_Bh[c*768 + r] = fp16(sum_s ...)
//           r=(i*12+I)*8+a, c=(o*12+O)*16+b
// ============================================================================
__global__ void compute_Wt_kernel(const float* __restrict__ W1) {
    int IO = blockIdx.x;
    int I = IO / 12, O = IO % 12;
    int t = threadIdx.x;
    int o = t >> 4, b = t & 15;

    __shared__ float sW1[32][128];
    __shared__ float sT[32][128];

    float acc[64];
#pragma unroll
    for (int i = 0; i < 64; i++) acc[i] = 0.f;

    for (int s0 = 0; s0 < NS; s0 += 32) {
        int ns = min(32, NS - s0);
        for (int j = t; j < ns * 128; j += 256) {
            int ss = j >> 7, io = j & 127;
            sW1[ss][io] = W1[io * NS + s0 + ss];
        }
        for (int j = t; j < ns * 128; j += 256) {
            int ss = j >> 7, ab = j & 127;
            sT[ss][ab] = g_T[((size_t)(s0 + ss) * 144 + IO) * 128 + ab];
        }
        __syncthreads();
        for (int ss = 0; ss < ns; ss++) {
            float w1v[8], tv[8];
#pragma unroll
            for (int i = 0; i < 8; i++) w1v[i] = sW1[ss][i * 16 + o];
#pragma unroll
            for (int a = 0; a < 8; a++) tv[a] = sT[ss][a * 16 + b];
#pragma unroll
            for (int i = 0; i < 8; i++)
#pragma unroll
                for (int a = 0; a < 8; a++)
                    acc[i * 8 + a] += w1v[i] * tv[a];
        }
        __syncthreads();
    }

    int c = (o * 12 + O) * 16 + b;
#pragma unroll
    for (int i = 0; i < 8; i++)
#pragma unroll
        for (int a = 0; a < 8; a++) {
            int r = (i * 12 + I) * 8 + a;
            g_Bh[(size_t)c * K_IN + r] = __float2half_rn(acc[i * 8 + a]);
        }
}

// ============================================================================
// Kernel 3: GEMM via mma.sync fp16 (fp32 accum). 256 threads = 8 warps
// (2m x 4n), warp tile 64x32, BK=64, 2-stage cp.async, 2 CTAs/SM.
// Fragment addresses: addr(ks) = base ^ (ks<<5)  (swizzle bit algebra).
// C stores via __stcs (evict-first).
// ============================================================================
__global__ __launch_bounds__(256, 2)
void gemm_mma_kernel(const float* __restrict__ bias, float* __restrict__ C) {
    extern __shared__ unsigned char smem[];
    const uint32_t sbase = smem_u32(smem);

    const int tid  = threadIdx.x;
    const int wid  = tid >> 5;
    const int lane = tid & 31;
    const int m0 = blockIdx.y * BM;
    const int n0 = blockIdx.x * BN;
    const int warp_m = (wid & 1) * 64;   // 0,64
    const int warp_n = (wid >> 1) * 32;  // 0,32,64,96

    float acc[4][4][4];
#pragma unroll
    for (int i = 0; i < 4; i++)
#pragma unroll
        for (int j = 0; j < 4; j++)
#pragma unroll
            for (int q = 0; q < 4; q++) acc[i][j][q] = 0.f;

    // ---- stage loader ----
    auto load_stage = [&](int stage, int it) {
        int k0 = it * BK;
        uint32_t sA = sbase + stage * STAGE_BYTES;
        uint32_t sB = sA + A_STAGE_BYTES;
#pragma unroll
        for (int j = 0; j < 4; j++) {
            int id  = tid + j * 256;
            int row = id >> 3;
            int c   = id & 7;
            cp16(sA + swz128(row, c), g_Ah + (size_t)(m0 + row) * K_IN + k0 + c * 8);
        }
#pragma unroll
        for (int j = 0; j < 4; j++) {
            int id  = tid + j * 256;
            int row = id >> 3;
            int c   = id & 7;
            cp16(sB + swz128(row, c), g_Bh + (size_t)(n0 + row) * K_IN + k0 + c * 8);
        }
    };

    const int fr = lane & 15;
    const int fc = lane >> 4;

    // Per-warp fragment base offsets (ks=0); addr(ks) = base ^ (ks<<5).
    uint32_t aOff[4], bOff[2];
#pragma unroll
    for (int mt = 0; mt < 4; mt++)
        aOff[mt] = swz128(warp_m + mt * 16 + fr, fc);
#pragma unroll
    for (int nt = 0; nt < 2; nt++)
        bOff[nt] = swz128(warp_n + nt * 16 + fr, fc) + A_STAGE_BYTES;

    // Prologue: stage 0
    load_stage(0, 0); CP_COMMIT();

    for (int it = 0; it < NIT; it++) {
        __syncthreads();           // all warps done computing iter it-1
        if (it + 1 < NIT) load_stage((it + 1) & 1, it + 1);
        CP_COMMIT();
        CP_WAIT1();                // stage it&1 landed (lookahead group may fly)
        __syncthreads();           // cross-thread visibility of stage it&1

        uint32_t sS = sbase + (it & 1) * STAGE_BYTES;

#pragma unroll
        for (int ks = 0; ks < 4; ks++) {
            const uint32_t kx = (uint32_t)(ks << 5);
            uint32_t aF[4][4];
#pragma unroll
            for (int mt = 0; mt < 4; mt++) {
                LDMATRIX_X4(aF[mt][0], aF[mt][1], aF[mt][2], aF[mt][3],
                            sS + (aOff[mt] ^ kx));
            }
            uint32_t bF[2][4];
#pragma unroll
            for (int nt = 0; nt < 2; nt++) {
                LDMATRIX_X4(bF[nt][0], bF[nt][1], bF[nt][2], bF[nt][3],
                            sS + (bOff[nt] ^ kx));
            }
#pragma unroll
            for (int mt = 0; mt < 4; mt++)
#pragma unroll
                for (int nt = 0; nt < 2; nt++)
#pragma unroll
                    for (int p = 0; p < 2; p++) {
                        MMA_F16(acc[mt][nt * 2 + p],
                                aF[mt][0], aF[mt][1], aF[mt][2], aF[mt][3],
                                bF[nt][p], bF[nt][2 + p]);
                    }
        }
    }

    // ---- Epilogue: bias + streaming store ----
    const int g = lane >> 2, tig = lane & 3;
    float bv[4][2];
#pragma unroll
    for (int nn = 0; nn < 4; nn++) {
        int col = n0 + warp_n + nn * 8 + tig * 2;
        bv[nn][0] = __ldg(&bias[col]);
        bv[nn][1] = __ldg(&bias[col + 1]);
    }
#pragma unroll
    for (int mt = 0; mt < 4; mt++) {
        int r0 = m0 + warp_m + mt * 16 + g;
        int r1 = r0 + 8;
#pragma unroll
        for (int nn = 0; nn < 4; nn++) {
            int col = n0 + warp_n + nn * 8 + tig * 2;
            float2 v0 = make_float2(acc[mt][nn][0] + bv[nn][0], acc[mt][nn][1] + bv[nn][1]);
            float2 v1 = make_float2(acc[mt][nn][2] + bv[nn][0], acc[mt][nn][3] + bv[nn][1]);
            __stcs(reinterpret_cast<float2*>(&C[(size_t)r0 * N_OUT + col]), v0);
            __stcs(reinterpret_cast<float2*>(&C[(size_t)r1 * N_OUT + col]), v1);
        }
    }
}

// ============================================================================
// Launch. Inputs: x, W_1, W_2, W_3, b. Output fp32 (32768, 3072).
// ============================================================================
extern "C" void kernel_launch(void* const* d_in, const int* in_sizes, int n_in,
                              void* d_out, int out_size) {
    const float* x  = (const float*)d_in[0];
    const float* W1 = (const float*)d_in[1];
    const float* W2 = (const float*)d_in[2];
    const float* W3 = (const float*)d_in[3];
    const float* b  = (const float*)d_in[4];
    float* out = (float*)d_out;

    cudaFuncSetAttribute(gemm_mma_kernel,
                         cudaFuncAttributeMaxDynamicSharedMemorySize, SMEM_TOTAL);

    prep_kernel<<<CVT_BLOCKS + T_GRID_BLOCKS, 128>>>(x, W2, W3);
    compute_Wt_kernel<<<144, 256>>>(W1);
    gemm_mma_kernel<<<dim3(N_TILES, M_TILES), 256, SMEM_TOTAL>>>(b, out);
}